// round 1
// baseline (speedup 1.0000x reference)
#include <cuda_runtime.h>

// Problem constants
#define BN    32
#define CIN   256
#define COUT  256
#define HIN   64
#define WIN   64
#define OH    32
#define OW    32
#define CHUNK 4

// Scratch: weights transposed to [ci][tap][cout] for coalesced loads.
__device__ float g_wT[CIN * 9 * COUT];

__global__ void transpose_w_kernel(const float* __restrict__ w) {
    int idx = blockIdx.x * blockDim.x + threadIdx.x;  // over co*ci*9 (coalesced read)
    if (idx >= COUT * CIN * 9) return;
    int co  = idx / (CIN * 9);
    int rem = idx % (CIN * 9);  // ci*9 + tap
    g_wT[rem * COUT + co] = w[idx];
}

__device__ __forceinline__ void fma2(unsigned long long& d, unsigned long long a,
                                     unsigned long long b) {
    asm("fma.rn.f32x2 %0, %1, %2, %0;" : "+l"(d) : "l"(a), "l"(b));
}

// Block: 64 couts x (8 rows x 32 cols) x 1 batch. 256 threads.
// Thread (tx=ow, ty=cout-group): 8 rows x 8 couts = 32 f32x2 accumulators.
__global__ __launch_bounds__(256, 2)
void conv_main_kernel(const float* __restrict__ x, float* __restrict__ out) {
    // Inputs pre-duplicated (v,v) and split by column parity:
    //   even cols 0,2,..,62  -> sInE[.][.][j], col = 2j      (kw=1 tap)
    //   odd  cols -1,1,..,63 -> sInO[.][.][j], col = 2j-1    (kw=0: j=tx, kw=2: j=tx+1)
    __shared__ __align__(16) unsigned long long sInE[CHUNK][17][32];
    __shared__ __align__(16) unsigned long long sInO[CHUNK][17][33];
    __shared__ __align__(16) float sW[CHUNK][9][64];

    const int tid = threadIdx.x;
    const int tx = tid & 31;   // ow
    const int ty = tid >> 5;   // cout group (8 couts each)
    const int co_base = blockIdx.x * 64;
    const int R = blockIdx.y * 8;        // output row base
    const int b = blockIdx.z;

    const float* xb = x + (size_t)b * CIN * HIN * WIN;

    unsigned long long acc[8][4];
#pragma unroll
    for (int r = 0; r < 8; r++)
#pragma unroll
        for (int c = 0; c < 4; c++) acc[r][c] = 0ULL;

    for (int ci0 = 0; ci0 < CIN; ci0 += CHUNK) {
        __syncthreads();
        // ---- load input chunk (coalesced over col) ----
        for (int idx = tid; idx < CHUNK * 17 * 64; idx += 256) {
            int cc  = idx / (17 * 64);
            int rr  = (idx / 64) % 17;
            int col = idx & 63;
            int ir  = 2 * R - 1 + rr;  // input row (can be -1 at top tile)
            float v = 0.0f;
            if (ir >= 0) v = xb[((ci0 + cc) * HIN + ir) * WIN + col];
            float2 f2 = make_float2(v, v);
            unsigned long long vv = *reinterpret_cast<unsigned long long*>(&f2);
            if (col & 1) sInO[cc][rr][(col + 1) >> 1] = vv;
            else         sInE[cc][rr][col >> 1] = vv;
        }
        // left padding column (col = -1) -> odd index 0
        for (int idx = tid; idx < CHUNK * 17; idx += 256)
            sInO[idx / 17][idx % 17][0] = 0ULL;
        // ---- load weight chunk (coalesced 64-float runs from g_wT) ----
        for (int idx = tid; idx < CHUNK * 9 * 64; idx += 256) {
            int cc = idx / 576;
            int tp = (idx / 64) % 9;
            int co = idx & 63;
            sW[cc][tp][co] = g_wT[((ci0 + cc) * 9 + tp) * COUT + co_base + co];
        }
        __syncthreads();

        // ---- compute ----
#pragma unroll
        for (int cc = 0; cc < CHUNK; cc++) {
#pragma unroll
            for (int kh = 0; kh < 3; kh++) {
#pragma unroll
                for (int kw = 0; kw < 3; kw++) {
                    const unsigned long long* wrow =
                        reinterpret_cast<const unsigned long long*>(sW[cc][kh * 3 + kw]);
                    unsigned long long w0 = wrow[ty * 4 + 0];
                    unsigned long long w1 = wrow[ty * 4 + 1];
                    unsigned long long w2 = wrow[ty * 4 + 2];
                    unsigned long long w3 = wrow[ty * 4 + 3];
#pragma unroll
                    for (int r = 0; r < 8; r++) {
                        int lr = 2 * r + kh;  // 0..16
                        unsigned long long iv =
                            (kw == 0) ? sInO[cc][lr][tx]
                          : (kw == 1) ? sInE[cc][lr][tx]
                                      : sInO[cc][lr][tx + 1];
                        fma2(acc[r][0], iv, w0);
                        fma2(acc[r][1], iv, w1);
                        fma2(acc[r][2], iv, w2);
                        fma2(acc[r][3], iv, w3);
                    }
                }
            }
        }
    }

    // ---- write out: acc[r][c] holds couts (co_base+ty*8+2c, +1) at (R+r, tx) ----
#pragma unroll
    for (int r = 0; r < 8; r++) {
#pragma unroll
        for (int c = 0; c < 4; c++) {
            float2 res = *reinterpret_cast<float2*>(&acc[r][c]);
            int co = co_base + ty * 8 + 2 * c;
            size_t o = (((size_t)b * COUT + co) * OH + (R + r)) * OW + tx;
            out[o] = res.x;
            out[o + (size_t)OH * OW] = res.y;
        }
    }
}

extern "C" void kernel_launch(void* const* d_in, const int* in_sizes, int n_in,
                              void* d_out, int out_size) {
    const float* x = (const float*)d_in[0];       // [32,256,64,64]
    const float* w = (const float*)d_in[1];       // [256,256,3,3]
    float* out = (float*)d_out;                   // [32,256,32,32]
    (void)in_sizes; (void)n_in; (void)out_size;

    int wtot = COUT * CIN * 9;
    transpose_w_kernel<<<(wtot + 255) / 256, 256>>>(w);

    dim3 grid(COUT / 64, OH / 8, BN);  // (4, 4, 32) = 512 blocks
    conv_main_kernel<<<grid, 256>>>(x, out);
}

// round 3
// speedup vs baseline: 5.3939x; 5.3939x over previous
#include <cuda_runtime.h>
#include <cstdint>

#define BN   32
#define CIN  256
#define COUT 256
#define HIN  64
#define WIN  64
#define OH   32
#define OW   32

#define CI_STRIDE 648            // floats per ci plane in xs: 9 rows * 72
#define ROW_STRIDE 72
#define SBUF (16 * CI_STRIDE)    // 10368 floats per buffer
#define SM_BYTES (2 * SBUF * 4)  // 82944 B

#define NWA (9 * 32 * 16 * 128)  // g_wA floats: tap x kstep x mtile x (lane*4)

// Weights in mma-fragment order: [tap][ks][mt][lane][q]
__device__ __align__(16) float g_wA[NWA];

__device__ __forceinline__ uint32_t smem_u32(const void* p) {
    uint32_t a;
    asm("{ .reg .u64 t; cvta.to.shared.u64 t, %1; cvt.u32.u64 %0, t; }" : "=r"(a) : "l"(p));
    return a;
}

// ---------------- prologue: weights -> tf32, fragment order ----------------
__global__ void prep_w(const float* __restrict__ w) {
    int idx = blockIdx.x * 256 + threadIdx.x;
    if (idx >= NWA) return;
    int q  = idx & 3;
    int l  = (idx >> 2) & 31;
    int mt = (idx >> 7) & 15;
    int ks = (idx >> 11) & 31;
    int t  = idx >> 16;
    int m  = mt * 16 + (l >> 2) + (q & 1) * 8;
    int ci = ks * 8 + (l & 3) + ((q >> 1) & 1) * 4;
    float v = w[((size_t)m * CIN + ci) * 9 + t];
    float o;
    asm("cvt.rna.tf32.f32 %0, %1;" : "=f"(o) : "f"(v));
    g_wA[idx] = o;
}

// ---------------- main: TF32 mma.sync implicit-GEMM conv ----------------
__global__ __launch_bounds__(256, 2)
void conv_mma(const float* __restrict__ x, float* __restrict__ out) {
    extern __shared__ __align__(16) float xs[];
    const int tid  = threadIdx.x;
    const int lane = tid & 31;
    const int warp = tid >> 5;
    const int warpM = warp >> 2;   // 0..1 : 64-cout slab
    const int warpN = warp & 3;    // 0..3 : output row (r) within tile
    const int gid = lane >> 2;     // n within 8-tile / m-row within 8
    const int tig = lane & 3;      // k within 4
    const int bx = blockIdx.x;
    const int R  = blockIdx.y * 4;
    const int b  = blockIdx.z;

    const uint32_t xs_base = smem_u32(xs);

    // -------- fill group g's x tile into buffer buf --------
    // Layout per ci plane: 9 rows * 72 floats. Data col offset = iw + 4
    // (so 16B cp.async chunks stay aligned); offsets 0..3 zeroed -> iw=-1 pad at 3.
    auto fill = [&](int g, int buf) {
        const float* xg = x + ((size_t)b * CIN + g * 16) * (HIN * WIN);
        const uint32_t dstb = xs_base + buf * (SBUF * 4);
        if (tid < 144) {
            int ci = tid / 9, row = tid % 9;
            *(float4*)((char*)xs + (size_t)buf * SBUF * 4 +
                       (ci * CI_STRIDE + row * ROW_STRIDE) * 4) = make_float4(0.f, 0.f, 0.f, 0.f);
        }
        for (int i = tid; i < 2304; i += 256) {
            int ci = i / 144, rem = i % 144;
            int row = rem >> 4, c4 = rem & 15;
            int ir = 2 * R - 1 + row;
            uint32_t d = dstb + (ci * CI_STRIDE + row * ROW_STRIDE + 4 + c4 * 4) * 4;
            const float* s = xg + (size_t)ci * (HIN * WIN) + ir * WIN + c4 * 4;
            int sz = (ir >= 0) ? 16 : 0;
            asm volatile("cp.async.ca.shared.global [%0], [%1], 16, %2;"
                         :: "r"(d), "l"(s), "r"(sz));
        }
    };

    float acc[4][4][4];
#pragma unroll
    for (int mt = 0; mt < 4; mt++)
#pragma unroll
        for (int nt = 0; nt < 4; nt++)
#pragma unroll
            for (int q = 0; q < 4; q++) acc[mt][nt][q] = 0.f;

    fill(0, 0);
    asm volatile("cp.async.commit_group;" ::: "memory");
    asm volatile("cp.async.wait_group 0;" ::: "memory");
    __syncthreads();

    // Per-thread invariant part of B address (bytes within buffer):
    // float idx = tig*CI_STRIDE + gid*2 + 3 + 2*warpN*ROW_STRIDE (+ kh*72 + kw + nt*16 + ksl*8*CI_STRIDE)
    const uint32_t tb0 = (uint32_t)(tig * CI_STRIDE + gid * 2 + 3 + 2 * warpN * ROW_STRIDE) * 4;

    for (int g = 0; g < 16; g++) {
        if (g < 15) fill(g + 1, (g + 1) & 1);
        asm volatile("cp.async.commit_group;" ::: "memory");

        const uint32_t bufb = xs_base + (g & 1) * (SBUF * 4);
        int kh = 0, kw = 0;
        for (int t = 0; t < 9; t++) {
#pragma unroll
            for (int ksl = 0; ksl < 2; ksl++) {
                const int ks = g * 2 + ksl;
                // ---- A fragments: 4 coalesced LDG.128 from fragment-ordered g_wA ----
                const float4* ap = (const float4*)g_wA +
                    ((size_t)((t * 32 + ks) * 16 + bx * 8 + warpM * 4)) * 32 + lane;
                float4 A0f = ap[0], A1f = ap[32], A2f = ap[64], A3f = ap[96];
                uint4 A0 = *(uint4*)&A0f, A1 = *(uint4*)&A1f,
                      A2 = *(uint4*)&A2f, A3 = *(uint4*)&A3f;

                // ---- B fragments: direct LDS from staged x + RNA tf32 round ----
                const uint32_t baddr = bufb + tb0 +
                    (uint32_t)(kh * ROW_STRIDE + kw + ksl * 8 * CI_STRIDE) * 4;
                uint32_t b0[4], b1[4];
#pragma unroll
                for (int nt = 0; nt < 4; nt++) {
                    float v0, v1;
                    asm volatile("ld.shared.f32 %0, [%1];" : "=f"(v0) : "r"(baddr + nt * 64));
                    asm volatile("ld.shared.f32 %0, [%1];" : "=f"(v1)
                                 : "r"(baddr + nt * 64 + 4 * CI_STRIDE * 4));
                    asm("cvt.rna.tf32.f32 %0, %1;" : "=r"(b0[nt]) : "f"(v0));
                    asm("cvt.rna.tf32.f32 %0, %1;" : "=r"(b1[nt]) : "f"(v1));
                }

#define MMA_ONE(ACC, A, NT)                                                    \
    asm volatile("mma.sync.aligned.m16n8k8.row.col.f32.tf32.tf32.f32 "         \
                 "{%0,%1,%2,%3},{%4,%5,%6,%7},{%8,%9},{%0,%1,%2,%3};"          \
                 : "+f"(ACC[0]), "+f"(ACC[1]), "+f"(ACC[2]), "+f"(ACC[3])      \
                 : "r"(A.x), "r"(A.y), "r"(A.z), "r"(A.w),                     \
                   "r"(b0[NT]), "r"(b1[NT]))
#pragma unroll
                for (int nt = 0; nt < 4; nt++) {
                    MMA_ONE(acc[0][nt], A0, nt);
                    MMA_ONE(acc[1][nt], A1, nt);
                    MMA_ONE(acc[2][nt], A2, nt);
                    MMA_ONE(acc[3][nt], A3, nt);
                }
#undef MMA_ONE
            }
            kw++;
            if (kw == 3) { kw = 0; kh++; }
        }
        asm volatile("cp.async.wait_group 0;" ::: "memory");
        __syncthreads();
    }

    // ---------------- epilogue ----------------
    const int orow = R + warpN;
#pragma unroll
    for (int mt = 0; mt < 4; mt++) {
        int co = bx * 128 + warpM * 64 + mt * 16 + gid;
        float* base = out + (((size_t)b * COUT + co) * OH + orow) * OW;
#pragma unroll
        for (int nt = 0; nt < 4; nt++) {
            int ow0 = nt * 8 + tig * 2;
            *(float2*)(base + ow0) = make_float2(acc[mt][nt][0], acc[mt][nt][1]);
            *(float2*)(base + 8 * OH * OW + ow0) = make_float2(acc[mt][nt][2], acc[mt][nt][3]);
        }
    }
}

extern "C" void kernel_launch(void* const* d_in, const int* in_sizes, int n_in,
                              void* d_out, int out_size) {
    const float* x = (const float*)d_in[0];   // [32,256,64,64]
    const float* w = (const float*)d_in[1];   // [256,256,3,3]
    float* out = (float*)d_out;               // [32,256,32,32]
    (void)in_sizes; (void)n_in; (void)out_size;

    cudaFuncSetAttribute(conv_mma, cudaFuncAttributeMaxDynamicSharedMemorySize, SM_BYTES);

    prep_w<<<(NWA + 255) / 256, 256>>>(w);

    dim3 grid(2, 8, BN);  // 512 CTAs
    conv_mma<<<grid, 256, SM_BYTES>>>(x, out);
}